// round 3
// baseline (speedup 1.0000x reference)
#include <cuda_runtime.h>
#include <cstdint>

#define N_NODES 50000
#define N_EDGES 800000
#define H 128
#define RDIM 6
#define NTYPES 95
#define NKEYS (NTYPES * 3)      // 285
#define TM 64                   // edges per tile
#define KP 132                  // padded row stride (floats) for 128-wide tiles
#define NTILES (N_EDGES / TM)   // 12500

// Scratch (allocation-free rule: __device__ globals)
__device__ __align__(16) float g_tableA[NKEYS * H];
__device__ __align__(16) float g_tableB[NKEYS * H];
__device__ int g_key[N_NODES];

// ---------------------------------------------------------------------------
// helpers
// ---------------------------------------------------------------------------
__device__ __forceinline__ float silu_f(float v) {
    // v * sigmoid(v) = v / (1 + e^-v); __expf + __fdividef = 2 MUFU
    return __fdividef(v, 1.0f + __expf(-v));
}

__device__ __forceinline__ float to_tf32(float v) {
    uint32_t u;
    asm("cvt.rna.tf32.f32 %0, %1;" : "=r"(u) : "f"(v));
    return __uint_as_float(u);
}

__device__ __forceinline__ void mma_tf32(float (&d)[4],
                                         float a0, float a1, float a2, float a3,
                                         float b0, float b1) {
    uint32_t A0 = __float_as_uint(a0), A1 = __float_as_uint(a1);
    uint32_t A2 = __float_as_uint(a2), A3 = __float_as_uint(a3);
    uint32_t B0 = __float_as_uint(b0), B1 = __float_as_uint(b1);
    asm volatile(
        "mma.sync.aligned.m16n8k8.row.col.f32.tf32.tf32.f32 "
        "{%0,%1,%2,%3}, {%4,%5,%6,%7}, {%8,%9}, {%0,%1,%2,%3};\n"
        : "+f"(d[0]), "+f"(d[1]), "+f"(d[2]), "+f"(d[3])
        : "r"(A0), "r"(A1), "r"(A2), "r"(A3), "r"(B0), "r"(B1));
}

// ---------------------------------------------------------------------------
// kernel 1: key[n] = x[n]*3 + s[n]
// ---------------------------------------------------------------------------
__global__ void key_kernel(const int* __restrict__ x, const int* __restrict__ s) {
    int n = blockIdx.x * blockDim.x + threadIdx.x;
    if (n < N_NODES) g_key[n] = x[n] * 3 + s[n];
}

// ---------------------------------------------------------------------------
// kernel 2: per-(type,spin) tables
// tableA[t,c,o] = emb_w[t] . lin_w[o, 0:128]  + sum_q (spin_w[q,c]+spin_b[q]) * lin_w[o,128+q] + lin_b[o]
// tableB[t,c,o] = emb_w[t] . lin_w[o,131:259] + sum_q (spin_w[q,c]+spin_b[q]) * lin_w[o,259+q]
// ---------------------------------------------------------------------------
__global__ void table_kernel(const float* __restrict__ emb_w,
                             const float* __restrict__ spin_w,
                             const float* __restrict__ spin_b,
                             const float* __restrict__ lin_w,
                             const float* __restrict__ lin_b) {
    __shared__ float sh[H];
    const int b = blockIdx.x;
    const int t = b / 3, c = b % 3;
    const int tid = threadIdx.x, lane = tid & 31, w = tid >> 5;
    sh[tid] = emb_w[t * H + tid];
    const float sp0 = spin_w[0 * 3 + c] + spin_b[0];
    const float sp1 = spin_w[1 * 3 + c] + spin_b[1];
    const float sp2 = spin_w[2 * 3 + c] + spin_b[2];
    __syncthreads();
    for (int o = w * 32; o < w * 32 + 32; o++) {
        const float* row = lin_w + o * 390;
        float pa = 0.f, pb = 0.f;
#pragma unroll
        for (int u = 0; u < 4; u++) {
            int k = lane * 4 + u;
            pa += row[k] * sh[k];
            pb += row[131 + k] * sh[k];
        }
#pragma unroll
        for (int d = 16; d > 0; d >>= 1) {
            pa += __shfl_xor_sync(0xffffffffu, pa, d);
            pb += __shfl_xor_sync(0xffffffffu, pb, d);
        }
        if (lane == 0) {
            float sa = sp0 * row[128] + sp1 * row[129] + sp2 * row[130];
            float sb = sp0 * row[259] + sp1 * row[260] + sp2 * row[261];
            g_tableA[b * H + o] = pa + sa + lin_b[o];
            g_tableB[b * H + o] = pb + sb;
        }
    }
}

// ---------------------------------------------------------------------------
// kernel 3: persistent edge kernel
// ---------------------------------------------------------------------------
struct EdgeSmem {
    float W[H * KP];      // W5 (tf32), [n][k]          67584 B
    float Rt[TM * KP];    // R tile, then C tile        33792 B
    float rb[TM * 8];     // rbf tile (padded to 8)      2048 B
    float rbW[RDIM * H];  // rbf_w transposed [q][k]     3072 B
    float rbB[H];         //                              512 B
    int kA[TM];
    int kB[TM];           //                              512 B
};

__global__ __launch_bounds__(128) void edge_kernel(
    const float* __restrict__ rbf,
    const int* __restrict__ gi,
    const int* __restrict__ gj,
    const float* __restrict__ rbf_w,
    const float* __restrict__ rbf_b,
    const float* __restrict__ lin_w,
    float* __restrict__ out) {
    extern __shared__ __align__(16) char smem_raw[];
    EdgeSmem& S = *reinterpret_cast<EdgeSmem*>(smem_raw);

    const int tid = threadIdx.x;
    const int lane = tid & 31;
    const int w = tid >> 5;
    const int m0 = w * 16;
    const int g = lane >> 2;   // groupID
    const int tg = lane & 3;   // thread-in-group

    // Stage W5 (tf32) and rbf weights once per CTA
    for (int idx = tid; idx < H * H; idx += 128) {
        int n = idx >> 7, k = idx & 127;
        S.W[n * KP + k] = to_tf32(lin_w[n * 390 + 262 + k]);
    }
    for (int idx = tid; idx < RDIM * H; idx += 128) {
        int q = idx >> 7, k = idx & 127;
        S.rbW[q * H + k] = rbf_w[k * RDIM + q];
    }
    S.rbB[tid] = rbf_b[tid];
    __syncthreads();

    // Per-thread rbf weights for column k = tid
    float wq[RDIM];
#pragma unroll
    for (int q = 0; q < RDIM; q++) wq[q] = S.rbW[q * H + tid];
    const float bk = S.rbB[tid];

    for (int tile = blockIdx.x; tile < NTILES; tile += gridDim.x) {
        const int e0 = tile * TM;

        // --- load indices/keys + rbf tile -----------------------------------
        if (tid < TM) {
            S.kA[tid] = g_key[gi[e0 + tid]];
            S.kB[tid] = g_key[gj[e0 + tid]];
        }
        for (int idx = tid; idx < TM * RDIM; idx += 128) {
            S.rb[(idx / RDIM) * 8 + (idx % RDIM)] = rbf[(size_t)e0 * RDIM + idx];
        }
        __syncthreads();

        // --- R tile: r[m][k=tid] = silu(rbf[m].wq + bk), tf32 ---------------
#pragma unroll 4
        for (int m = 0; m < TM; m++) {
            float acc = bk;
#pragma unroll
            for (int q = 0; q < RDIM; q++) acc = fmaf(S.rb[m * 8 + q], wq[q], acc);
            S.Rt[m * KP + tid] = to_tf32(silu_f(acc));
        }
        __syncthreads();

        // --- GEMM: C[m0:m0+16, 0:128] += R . W5^T ---------------------------
        float acc[16][4];
#pragma unroll
        for (int nt = 0; nt < 16; nt++) {
            acc[nt][0] = 0.f; acc[nt][1] = 0.f; acc[nt][2] = 0.f; acc[nt][3] = 0.f;
        }
#pragma unroll
        for (int kt = 0; kt < 16; kt++) {
            const int k0 = kt * 8;
            const float a0 = S.Rt[(m0 + g) * KP + k0 + tg];
            const float a1 = S.Rt[(m0 + g + 8) * KP + k0 + tg];
            const float a2 = S.Rt[(m0 + g) * KP + k0 + tg + 4];
            const float a3 = S.Rt[(m0 + g + 8) * KP + k0 + tg + 4];
#pragma unroll
            for (int nt = 0; nt < 16; nt++) {
                const int n = nt * 8 + g;
                const float b0 = S.W[n * KP + k0 + tg];
                const float b1 = S.W[n * KP + k0 + tg + 4];
                mma_tf32(acc[nt], a0, a1, a2, a3, b0, b1);
            }
        }
        // store C into Rt (each warp overwrites only its own 16 rows)
#pragma unroll
        for (int nt = 0; nt < 16; nt++) {
            const int n = nt * 8 + 2 * tg;
            S.Rt[(m0 + g) * KP + n]         = acc[nt][0];
            S.Rt[(m0 + g) * KP + n + 1]     = acc[nt][1];
            S.Rt[(m0 + g + 8) * KP + n]     = acc[nt][2];
            S.Rt[(m0 + g + 8) * KP + n + 1] = acc[nt][3];
        }
        __syncthreads();

        // --- epilogue: out[e] = silu(tableA[keyA] + tableB[keyB] + C) -------
#pragma unroll 4
        for (int m = m0; m < m0 + 16; m++) {
            const float4 a  = *reinterpret_cast<const float4*>(&g_tableA[S.kA[m] * H + lane * 4]);
            const float4 b  = *reinterpret_cast<const float4*>(&g_tableB[S.kB[m] * H + lane * 4]);
            const float4 cc = *reinterpret_cast<const float4*>(&S.Rt[m * KP + lane * 4]);
            float4 o;
            o.x = silu_f(a.x + b.x + cc.x);
            o.y = silu_f(a.y + b.y + cc.y);
            o.z = silu_f(a.z + b.z + cc.z);
            o.w = silu_f(a.w + b.w + cc.w);
            *reinterpret_cast<float4*>(&out[(size_t)(e0 + m) * H + lane * 4]) = o;
        }
        __syncthreads();
    }
}

// ---------------------------------------------------------------------------
extern "C" void kernel_launch(void* const* d_in, const int* in_sizes, int n_in,
                              void* d_out, int out_size) {
    const int*   x      = (const int*)d_in[0];
    const int*   s      = (const int*)d_in[1];
    const float* rbf    = (const float*)d_in[2];
    const int*   gi     = (const int*)d_in[3];
    const int*   gj     = (const int*)d_in[4];
    const float* emb_w  = (const float*)d_in[5];
    const float* spin_w = (const float*)d_in[6];
    const float* spin_b = (const float*)d_in[7];
    const float* rbf_w  = (const float*)d_in[8];
    const float* rbf_b  = (const float*)d_in[9];
    const float* lin_w  = (const float*)d_in[10];
    const float* lin_b  = (const float*)d_in[11];
    float* out = (float*)d_out;

    key_kernel<<<(N_NODES + 255) / 256, 256>>>(x, s);
    table_kernel<<<NKEYS, 128>>>(emb_w, spin_w, spin_b, lin_w, lin_b);

    const int smem = (int)sizeof(EdgeSmem);
    cudaFuncSetAttribute(edge_kernel, cudaFuncAttributeMaxDynamicSharedMemorySize, smem);
    edge_kernel<<<296, 128, smem>>>(rbf, gi, gj, rbf_w, rbf_b, lin_w, out);
}

// round 7
// speedup vs baseline: 1.4063x; 1.4063x over previous
#include <cuda_runtime.h>
#include <cuda_bf16.h>
#include <cstdint>

#define N_NODES 50000
#define N_EDGES 800000
#define H 128
#define RDIM 6
#define NTYPES 95
#define NKEYS (NTYPES * 3)      // 285
#define TM 64                   // edges per tile
#define NTILES (N_EDGES / TM)   // 12500
#define GRID 296                // 2 CTAs/SM * 148 SMs

// ---------------------------------------------------------------------------
// scratch (__device__ globals; allocation-free rule)
// ---------------------------------------------------------------------------
__device__ __align__(16) float g_tableA[NKEYS * H];
__device__ __align__(16) float g_tableB[NKEYS * H];
__device__ int g_key[N_NODES];

// ---------------------------------------------------------------------------
// helpers
// ---------------------------------------------------------------------------
__device__ __forceinline__ float silu_acc(float v) {        // accurate (epilogue)
    return __fdividef(v, 1.0f + __expf(-v));
}
__device__ __forceinline__ float silu_tanh(float v) {       // 1 MUFU (GEMM-input path)
    float t;
    asm("tanh.approx.f32 %0, %1;" : "=f"(t) : "f"(0.5f * v));
    return fmaf(0.5f * v, t, 0.5f * v);
}
__device__ __forceinline__ float to_tf32(float v) {
    uint32_t u;
    asm("cvt.rna.tf32.f32 %0, %1;" : "=r"(u) : "f"(v));
    return __uint_as_float(u);
}
__device__ __forceinline__ void mma_tf32(float (&d)[4],
                                         float a0, float a1, float a2, float a3,
                                         float b0, float b1) {
    uint32_t A0 = __float_as_uint(a0), A1 = __float_as_uint(a1);
    uint32_t A2 = __float_as_uint(a2), A3 = __float_as_uint(a3);
    uint32_t B0 = __float_as_uint(b0), B1 = __float_as_uint(b1);
    asm volatile(
        "mma.sync.aligned.m16n8k8.row.col.f32.tf32.tf32.f32 "
        "{%0,%1,%2,%3}, {%4,%5,%6,%7}, {%8,%9}, {%0,%1,%2,%3};\n"
        : "+f"(d[0]), "+f"(d[1]), "+f"(d[2]), "+f"(d[3])
        : "r"(A0), "r"(A1), "r"(A2), "r"(A3), "r"(B0), "r"(B1));
}

// A-fragment address (floats) in the per-(mtile,kt) padded blocks.
// Block (mt,kt) holds the 32-lane x 4-reg fragment of rows [mt*16, mt*16+16),
// k [kt*8, kt*8+8). Stride 132 floats (pad 4) to kill STS bank conflicts.
__device__ __forceinline__ int afrag_idx(int m, int k) {
    const int mt = m >> 4, g = m & 7, hi = (m >> 3) & 1;
    const int kt = k >> 3, tg = k & 3, khi = (k >> 2) & 1;
    return (mt * 16 + kt) * 132 + (g * 4 + tg) * 4 + hi + 2 * khi;
}

// ---------------------------------------------------------------------------
// kernel 1: key[n] = x[n]*3 + s[n]
// ---------------------------------------------------------------------------
__global__ void key_kernel(const int* __restrict__ x, const int* __restrict__ s) {
    int n = blockIdx.x * blockDim.x + threadIdx.x;
    if (n < N_NODES) g_key[n] = x[n] * 3 + s[n];
}

// ---------------------------------------------------------------------------
// kernel 2: per-(type,spin) tables (fp32, exact)
// ---------------------------------------------------------------------------
__global__ void table_kernel(const float* __restrict__ emb_w,
                             const float* __restrict__ spin_w,
                             const float* __restrict__ spin_b,
                             const float* __restrict__ lin_w,
                             const float* __restrict__ lin_b) {
    __shared__ float sh[H];
    const int b = blockIdx.x;
    const int t = b / 3, c = b % 3;
    const int tid = threadIdx.x, lane = tid & 31, w = tid >> 5;
    sh[tid] = emb_w[t * H + tid];
    const float sp0 = spin_w[0 * 3 + c] + spin_b[0];
    const float sp1 = spin_w[1 * 3 + c] + spin_b[1];
    const float sp2 = spin_w[2 * 3 + c] + spin_b[2];
    __syncthreads();
    for (int o = w * 32; o < w * 32 + 32; o++) {
        const float* row = lin_w + o * 390;
        float pa = 0.f, pb = 0.f;
#pragma unroll
        for (int u = 0; u < 4; u++) {
            int k = lane * 4 + u;
            pa += row[k] * sh[k];
            pb += row[131 + k] * sh[k];
        }
#pragma unroll
        for (int d = 16; d > 0; d >>= 1) {
            pa += __shfl_xor_sync(0xffffffffu, pa, d);
            pb += __shfl_xor_sync(0xffffffffu, pb, d);
        }
        if (lane == 0) {
            float sa = sp0 * row[128] + sp1 * row[129] + sp2 * row[130];
            float sb = sp0 * row[259] + sp1 * row[260] + sp2 * row[261];
            g_tableA[b * H + o] = pa + sa + lin_b[o];
            g_tableB[b * H + o] = pb + sb;
        }
    }
}

// ---------------------------------------------------------------------------
// kernel 3: persistent edge kernel — tf32 mma.sync, fragment-layout smem
// SMEM (floats): W 16384 | A/C 8448 | rb 512 | kA 64 | kB 64  = 101888 bytes
// ---------------------------------------------------------------------------
struct EdgeSmem {
    float W[16 * 8 * 32 * 4];   // [kt][ntp][lane][4] W fragments (tf32)  65536 B
    float A[4 * 16 * 132];      // A fragments, reused as C[64][132]      33792 B
    float rb[TM * 8];           // rbf tile                                2048 B
    int kA[TM];
    int kB[TM];
};

__global__ __launch_bounds__(128, 2) void edge_kernel(
    const float* __restrict__ rbf,
    const int* __restrict__ gi,
    const int* __restrict__ gj,
    const float* __restrict__ rbf_w,
    const float* __restrict__ rbf_b,
    const float* __restrict__ lin_w,
    float* __restrict__ out) {
    extern __shared__ __align__(16) char smem_raw[];
    EdgeSmem& S = *reinterpret_cast<EdgeSmem*>(smem_raw);

    const int tid  = threadIdx.x;
    const int lane = tid & 31;
    const int wid  = tid >> 5;
    const int g    = lane >> 2;
    const int tg   = lane & 3;
    const int wm   = wid & 1;   // m-half (32 rows)
    const int wn   = wid >> 1;  // n-half (64 cols)

    // ---- stage W fragments (tf32), pre-permuted into mma layout ------------
    for (int fi = tid; fi < 16384; fi += 128) {
        const int idx = fi & 3, ln = (fi >> 2) & 31, ntp = (fi >> 7) & 7, kt = fi >> 10;
        const int nt = 2 * ntp + (idx >> 1);
        const int n  = nt * 8 + (ln >> 2);
        const int k  = kt * 8 + (ln & 3) + 4 * (idx & 1);
        S.W[fi] = to_tf32(lin_w[n * 390 + 262 + k]);
    }

    // ---- per-thread rbf weights (thread owns cols k0=2c, k0+1; row half hh)
    const int c  = tid & 63;
    const int hh = tid >> 6;
    const int k0 = 2 * c;
    float w0[RDIM], w1[RDIM];
#pragma unroll
    for (int q = 0; q < RDIM; q++) {
        w0[q] = rbf_w[k0 * RDIM + q];
        w1[q] = rbf_w[(k0 + 1) * RDIM + q];
    }
    const float bia0 = rbf_b[k0], bia1 = rbf_b[k0 + 1];
    // phase-2 A-fragment base indices (kt, tg, khi fixed per thread)
    const int aw0 = afrag_idx(0, k0);      // offset for m=0 (add per-row part)
    __syncthreads();

    const float4* W4 = reinterpret_cast<const float4*>(S.W);

    for (int tile = blockIdx.x; tile < NTILES; tile += gridDim.x) {
        const int e0 = tile * TM;

        // -- phase 1: keys + rbf tile ---------------------------------------
        if (tid < TM) {
            S.kA[tid] = g_key[__ldg(gi + e0 + tid)];
            S.kB[tid] = g_key[__ldg(gj + e0 + tid)];
        }
        for (int idx = tid; idx < TM * RDIM; idx += 128)
            S.rb[(idx / RDIM) * 8 + (idx % RDIM)] = rbf[(size_t)e0 * RDIM + idx];
        __syncthreads();

        // -- phase 2: R = silu(rbf @ rbf_w^T + b) in fragment layout --------
#pragma unroll 4
        for (int r = 0; r < 32; r++) {
            const int m = hh * 32 + r;
            float z0 = bia0, z1 = bia1;
#pragma unroll
            for (int q = 0; q < RDIM; q++) {
                const float rv = S.rb[m * 8 + q];
                z0 = fmaf(rv, w0[q], z0);
                z1 = fmaf(rv, w1[q], z1);
            }
            const int mt = m >> 4, gg = m & 7, hi = (m >> 3) & 1;
            const int base = aw0 + mt * (16 * 132) + gg * 16 + hi;
            S.A[base]     = to_tf32(silu_tanh(z0));
            S.A[base + 4] = to_tf32(silu_tanh(z1));
        }
        __syncthreads();

        // -- phase 3: GEMM, warp (wm,wn) does C[wm*32..+32][wn*64..+64] -----
        float acc[2][8][4];
#pragma unroll
        for (int mi = 0; mi < 2; mi++)
#pragma unroll
            for (int j = 0; j < 8; j++) {
                acc[mi][j][0] = 0.f; acc[mi][j][1] = 0.f;
                acc[mi][j][2] = 0.f; acc[mi][j][3] = 0.f;
            }
        const float4* A4 = reinterpret_cast<const float4*>(S.A);
#pragma unroll
        for (int kt = 0; kt < 16; kt++) {
            const float4 av0 = A4[((wm * 2 + 0) * 16 + kt) * 33 + lane];
            const float4 av1 = A4[((wm * 2 + 1) * 16 + kt) * 33 + lane];
#pragma unroll
            for (int p = 0; p < 4; p++) {
                const float4 wv = W4[(kt * 8 + wn * 4 + p) * 32 + lane];
                mma_tf32(acc[0][2 * p],     av0.x, av0.y, av0.z, av0.w, wv.x, wv.y);
                mma_tf32(acc[0][2 * p + 1], av0.x, av0.y, av0.z, av0.w, wv.z, wv.w);
                mma_tf32(acc[1][2 * p],     av1.x, av1.y, av1.z, av1.w, wv.x, wv.y);
                mma_tf32(acc[1][2 * p + 1], av1.x, av1.y, av1.z, av1.w, wv.z, wv.w);
            }
        }
        __syncthreads();   // all warps done reading A before C overwrites it

        // -- phase 4: C -> smem (C[m][0..127], stride 132) ------------------
        float* C = S.A;
#pragma unroll
        for (int mi = 0; mi < 2; mi++) {
            const int row = wm * 32 + mi * 16 + g;
#pragma unroll
            for (int j = 0; j < 8; j++) {
                const int n = (wn * 8 + j) * 8 + 2 * tg;
                *reinterpret_cast<float2*>(&C[row * 132 + n]) =
                    make_float2(acc[mi][j][0], acc[mi][j][1]);
                *reinterpret_cast<float2*>(&C[(row + 8) * 132 + n]) =
                    make_float2(acc[mi][j][2], acc[mi][j][3]);
            }
        }
        __syncthreads();

        // -- phase 5: epilogue. warp w owns rows w*16..w*16+15 --------------
#pragma unroll 4
        for (int ml = 0; ml < 16; ml++) {
            const int m = wid * 16 + ml;
            const float4 a  = *reinterpret_cast<const float4*>(&g_tableA[S.kA[m] * H + lane * 4]);
            const float4 b  = *reinterpret_cast<const float4*>(&g_tableB[S.kB[m] * H + lane * 4]);
            const float4 cc = *reinterpret_cast<const float4*>(&C[m * 132 + lane * 4]);
            float4 o;
            o.x = silu_acc(a.x + b.x + cc.x);
            o.y = silu_acc(a.y + b.y + cc.y);
            o.z = silu_acc(a.z + b.z + cc.z);
            o.w = silu_acc(a.w + b.w + cc.w);
            *reinterpret_cast<float4*>(&out[(size_t)(e0 + m) * H + lane * 4]) = o;
        }
        __syncthreads();   // epilogue done before next tile's phase 1/2 writes
    }
}

// ---------------------------------------------------------------------------
extern "C" void kernel_launch(void* const* d_in, const int* in_sizes, int n_in,
                              void* d_out, int out_size) {
    const int*   x      = (const int*)d_in[0];
    const int*   s      = (const int*)d_in[1];
    const float* rbf    = (const float*)d_in[2];
    const int*   gi     = (const int*)d_in[3];
    const int*   gj     = (const int*)d_in[4];
    const float* emb_w  = (const float*)d_in[5];
    const float* spin_w = (const float*)d_in[6];
    const float* spin_b = (const float*)d_in[7];
    const float* rbf_w  = (const float*)d_in[8];
    const float* rbf_b  = (const float*)d_in[9];
    const float* lin_w  = (const float*)d_in[10];
    const float* lin_b  = (const float*)d_in[11];
    float* out = (float*)d_out;

    key_kernel<<<(N_NODES + 255) / 256, 256>>>(x, s);
    table_kernel<<<NKEYS, 128>>>(emb_w, spin_w, spin_b, lin_w, lin_b);

    const int smem = (int)sizeof(EdgeSmem);
    cudaFuncSetAttribute(edge_kernel, cudaFuncAttributeMaxDynamicSharedMemorySize, smem);
    edge_kernel<<<GRID, 128, smem>>>(rbf, gi, gj, rbf_w, rbf_b, lin_w, out);
}

// round 8
// speedup vs baseline: 1.6362x; 1.1635x over previous
#include <cuda_runtime.h>
#include <cuda_fp16.h>
#include <cstdint>

#define N_NODES 50000
#define N_EDGES 800000
#define H 128
#define RDIM 6
#define NTYPES 95
#define NKEYS (NTYPES * 3)      // 285
#define TM 64                   // edges per tile
#define NTILES (N_EDGES / TM)   // 12500
#define GRID 296                // 2 CTAs/SM * 148 SMs

// ---------------------------------------------------------------------------
// scratch (__device__ globals; allocation-free rule)
// ---------------------------------------------------------------------------
__device__ __align__(16) float g_tableA[NKEYS * H];
__device__ __align__(16) float g_tableB[NKEYS * H];
__device__ int g_key[N_NODES];

// ---------------------------------------------------------------------------
// helpers
// ---------------------------------------------------------------------------
__device__ __forceinline__ float silu_acc(float v) {        // accurate (epilogue)
    return __fdividef(v, 1.0f + __expf(-v));
}
__device__ __forceinline__ float silu_tanh(float v) {       // 1 MUFU (GEMM-input path)
    float t;
    asm("tanh.approx.f32 %0, %1;" : "=f"(t) : "f"(0.5f * v));
    return fmaf(0.5f * v, t, 0.5f * v);
}
__device__ __forceinline__ uint32_t pack_h2(float lo, float hi) {
    __half2 h = __floats2half2_rn(lo, hi);
    return *reinterpret_cast<uint32_t*>(&h);
}

// fp16 m16n8k16, f32 accumulate
__device__ __forceinline__ void mma_f16(float (&d)[4],
                                        uint32_t a0, uint32_t a1, uint32_t a2, uint32_t a3,
                                        uint32_t b0, uint32_t b1) {
    asm volatile(
        "mma.sync.aligned.m16n8k16.row.col.f32.f16.f16.f32 "
        "{%0,%1,%2,%3}, {%4,%5,%6,%7}, {%8,%9}, {%0,%1,%2,%3};\n"
        : "+f"(d[0]), "+f"(d[1]), "+f"(d[2]), "+f"(d[3])
        : "r"(a0), "r"(a1), "r"(a2), "r"(a3), "r"(b0), "r"(b1));
}

// ---------------------------------------------------------------------------
// kernel 1: key[n] = x[n]*3 + s[n]
// ---------------------------------------------------------------------------
__global__ void key_kernel(const int* __restrict__ x, const int* __restrict__ s) {
    int n = blockIdx.x * blockDim.x + threadIdx.x;
    if (n < N_NODES) g_key[n] = x[n] * 3 + s[n];
}

// ---------------------------------------------------------------------------
// kernel 2: per-(type,spin) tables (fp32, exact)
// ---------------------------------------------------------------------------
__global__ void table_kernel(const float* __restrict__ emb_w,
                             const float* __restrict__ spin_w,
                             const float* __restrict__ spin_b,
                             const float* __restrict__ lin_w,
                             const float* __restrict__ lin_b) {
    __shared__ float sh[H];
    const int b = blockIdx.x;
    const int t = b / 3, c = b % 3;
    const int tid = threadIdx.x, lane = tid & 31, w = tid >> 5;
    sh[tid] = emb_w[t * H + tid];
    const float sp0 = spin_w[0 * 3 + c] + spin_b[0];
    const float sp1 = spin_w[1 * 3 + c] + spin_b[1];
    const float sp2 = spin_w[2 * 3 + c] + spin_b[2];
    __syncthreads();
    for (int o = w * 32; o < w * 32 + 32; o++) {
        const float* row = lin_w + o * 390;
        float pa = 0.f, pb = 0.f;
#pragma unroll
        for (int u = 0; u < 4; u++) {
            int k = lane * 4 + u;
            pa += row[k] * sh[k];
            pb += row[131 + k] * sh[k];
        }
#pragma unroll
        for (int d = 16; d > 0; d >>= 1) {
            pa += __shfl_xor_sync(0xffffffffu, pa, d);
            pb += __shfl_xor_sync(0xffffffffu, pb, d);
        }
        if (lane == 0) {
            float sa = sp0 * row[128] + sp1 * row[129] + sp2 * row[130];
            float sb = sp0 * row[259] + sp1 * row[260] + sp2 * row[261];
            g_tableA[b * H + o] = pa + sa + lin_b[o];
            g_tableB[b * H + o] = pb + sb;
        }
    }
}

// ---------------------------------------------------------------------------
// kernel 3: persistent edge kernel — fp16 m16n8k16 mma.sync, fragment smem
//
// A fragments (fp16x2 words): block (mt 0..3, kc 0..7) = 132 words (pad 4);
//   word = (mt*8+kc)*132 + lane*4 + reg,  lane = g*4+tg, reg = 2*pb + hi
//   a0/a1 (pb=0): cols kc*16+2tg,+1; a2/a3 (pb=1): cols +8; hi: row g vs g+8
// W fragments (uint2): [(kc*16+nt)*32 + lane] = {b0,b1}
//   b0 = W[nt*8+g][kc*16+2tg,+1], b1 = same n, k+8
// ---------------------------------------------------------------------------
struct EdgeSmem {
    uint2    Wf[8 * 16 * 32];        // 32768 B  W fp16 fragments
    uint32_t Af[4 * 8 * 132];        // 16896 B  A fp16 fragments (132-word blocks)
    float    C[TM * 132];            // 33792 B  C fp32 (stride 132)
    float    rb[TM * 8];             //  2048 B
    int kA[TM];
    int kB[TM];                      //   512 B
};

__global__ __launch_bounds__(128, 2) void edge_kernel(
    const float* __restrict__ rbf,
    const int* __restrict__ gi,
    const int* __restrict__ gj,
    const float* __restrict__ rbf_w,
    const float* __restrict__ rbf_b,
    const float* __restrict__ lin_w,
    float* __restrict__ out) {
    extern __shared__ __align__(16) char smem_raw[];
    EdgeSmem& S = *reinterpret_cast<EdgeSmem*>(smem_raw);

    const int tid  = threadIdx.x;
    const int lane = tid & 31;
    const int wid  = tid >> 5;
    const int g    = lane >> 2;
    const int tg   = lane & 3;
    const int wm   = wid & 1;   // m-half (32 rows)
    const int wn   = wid >> 1;  // n-half (64 cols)

    // ---- stage W fragments (fp16), pre-permuted into mma B layout ----------
    for (int e = tid; e < 8 * 16 * 32; e += 128) {
        const int ln = e & 31, nt = (e >> 5) & 15, kc = e >> 9;
        const int n  = nt * 8 + (ln >> 2);
        const int k0 = kc * 16 + 2 * (ln & 3);
        const float* p = lin_w + n * 390 + 262 + k0;
        S.Wf[e] = make_uint2(pack_h2(p[0], p[1]), pack_h2(p[8], p[9]));
    }

    // ---- per-thread rbf weights (thread owns cols k0=2c, k0+1; row half hh)
    const int c  = tid & 63;
    const int hh = tid >> 6;
    const int k0 = 2 * c;
    float w0[RDIM], w1[RDIM];
#pragma unroll
    for (int q = 0; q < RDIM; q++) {
        w0[q] = rbf_w[k0 * RDIM + q];
        w1[q] = rbf_w[(k0 + 1) * RDIM + q];
    }
    const float bia0 = rbf_b[k0], bia1 = rbf_b[k0 + 1];
    // phase-2 A-fragment address pieces: kc, reg-base fixed per thread
    const int kc_t = c >> 3;              // k-chunk
    const int p_t  = c & 7;
    const int tg_t = p_t & 3;
    const int pb_t = p_t >> 2;            // 0 -> a0/a1, 1 -> a2/a3
    __syncthreads();

    for (int tile = blockIdx.x; tile < NTILES; tile += gridDim.x) {
        const int e0 = tile * TM;

        // -- phase 1: keys + rbf tile ---------------------------------------
        if (tid < TM) {
            S.kA[tid] = g_key[__ldg(gi + e0 + tid)];
            S.kB[tid] = g_key[__ldg(gj + e0 + tid)];
        }
        for (int idx = tid; idx < TM * RDIM; idx += 128)
            S.rb[(idx / RDIM) * 8 + (idx % RDIM)] = rbf[(size_t)e0 * RDIM + idx];
        __syncthreads();

        // -- phase 2: R = silu(rbf @ rbf_w^T + b), packed fp16x2 fragments --
#pragma unroll 4
        for (int r = 0; r < 32; r++) {
            const int m = hh * 32 + r;
            float z0 = bia0, z1 = bia1;
#pragma unroll
            for (int q = 0; q < RDIM; q++) {
                const float rv = S.rb[m * 8 + q];
                z0 = fmaf(rv, w0[q], z0);
                z1 = fmaf(rv, w1[q], z1);
            }
            const int mt = m >> 4, r16 = m & 15;
            const int hi = r16 >> 3, gg = r16 & 7;
            const int word = (mt * 8 + kc_t) * 132 + (gg * 4 + tg_t) * 4 + 2 * pb_t + hi;
            S.Af[word] = pack_h2(silu_tanh(z0), silu_tanh(z1));
        }
        __syncthreads();

        // -- phase 3: GEMM, warp (wm,wn) does C[wm*32..+32][wn*64..+64] -----
        float acc[2][8][4];
#pragma unroll
        for (int mi = 0; mi < 2; mi++)
#pragma unroll
            for (int j = 0; j < 8; j++) {
                acc[mi][j][0] = 0.f; acc[mi][j][1] = 0.f;
                acc[mi][j][2] = 0.f; acc[mi][j][3] = 0.f;
            }
        const uint4* A4 = reinterpret_cast<const uint4*>(S.Af);
#pragma unroll
        for (int kc = 0; kc < 8; kc++) {
            const uint4 av0 = A4[((wm * 2 + 0) * 8 + kc) * 33 + lane];
            const uint4 av1 = A4[((wm * 2 + 1) * 8 + kc) * 33 + lane];
#pragma unroll
            for (int j = 0; j < 8; j++) {
                const uint2 wv = S.Wf[(kc * 16 + wn * 8 + j) * 32 + lane];
                mma_f16(acc[0][j], av0.x, av0.y, av0.z, av0.w, wv.x, wv.y);
                mma_f16(acc[1][j], av1.x, av1.y, av1.z, av1.w, wv.x, wv.y);
            }
        }

        // -- phase 4: C -> smem (C[m][0..127], stride 132) ------------------
#pragma unroll
        for (int mi = 0; mi < 2; mi++) {
            const int row = wm * 32 + mi * 16 + g;
#pragma unroll
            for (int j = 0; j < 8; j++) {
                const int n = (wn * 8 + j) * 8 + 2 * tg;
                *reinterpret_cast<float2*>(&S.C[row * 132 + n]) =
                    make_float2(acc[mi][j][0], acc[mi][j][1]);
                *reinterpret_cast<float2*>(&S.C[(row + 8) * 132 + n]) =
                    make_float2(acc[mi][j][2], acc[mi][j][3]);
            }
        }
        __syncthreads();

        // -- phase 5: epilogue. warp w owns rows w*16..w*16+15 --------------
#pragma unroll 4
        for (int ml = 0; ml < 16; ml++) {
            const int m = wid * 16 + ml;
            const float4 a  = *reinterpret_cast<const float4*>(&g_tableA[S.kA[m] * H + lane * 4]);
            const float4 b  = *reinterpret_cast<const float4*>(&g_tableB[S.kB[m] * H + lane * 4]);
            const float4 cc = *reinterpret_cast<const float4*>(&S.C[m * 132 + lane * 4]);
            float4 o;
            o.x = silu_acc(a.x + b.x + cc.x);
            o.y = silu_acc(a.y + b.y + cc.y);
            o.z = silu_acc(a.z + b.z + cc.z);
            o.w = silu_acc(a.w + b.w + cc.w);
            *reinterpret_cast<float4*>(&out[(size_t)(e0 + m) * H + lane * 4]) = o;
        }
        __syncthreads();   // epilogue done before next tile overwrites rb/kA/Af/C
    }
}

// ---------------------------------------------------------------------------
extern "C" void kernel_launch(void* const* d_in, const int* in_sizes, int n_in,
                              void* d_out, int out_size) {
    const int*   x      = (const int*)d_in[0];
    const int*   s      = (const int*)d_in[1];
    const float* rbf    = (const float*)d_in[2];
    const int*   gi     = (const int*)d_in[3];
    const int*   gj     = (const int*)d_in[4];
    const float* emb_w  = (const float*)d_in[5];
    const float* spin_w = (const float*)d_in[6];
    const float* spin_b = (const float*)d_in[7];
    const float* rbf_w  = (const float*)d_in[8];
    const float* rbf_b  = (const float*)d_in[9];
    const float* lin_w  = (const float*)d_in[10];
    const float* lin_b  = (const float*)d_in[11];
    float* out = (float*)d_out;

    key_kernel<<<(N_NODES + 255) / 256, 256>>>(x, s);
    table_kernel<<<NKEYS, 128>>>(emb_w, spin_w, spin_b, lin_w, lin_b);

    const int smem = (int)sizeof(EdgeSmem);
    cudaFuncSetAttribute(edge_kernel, cudaFuncAttributeMaxDynamicSharedMemorySize, smem);
    edge_kernel<<<GRID, 128, smem>>>(rbf, gi, gj, rbf_w, rbf_b, lin_w, out);
}

// round 9
// speedup vs baseline: 2.5055x; 1.5313x over previous
#include <cuda_runtime.h>
#include <cuda_fp16.h>
#include <cstdint>

#define N_NODES 50000
#define N_EDGES 800000
#define H 128
#define RDIM 6
#define NTYPES 95
#define NKEYS (NTYPES * 3)      // 285
#define TM 64                   // edges per tile
#define NTILES (N_EDGES / TM)   // 12500
#define GRID 592                // 4 CTAs/SM * 148 SMs

// ---------------------------------------------------------------------------
// scratch (__device__ globals; allocation-free rule)
// ---------------------------------------------------------------------------
__device__ __align__(16) float g_tableA[NKEYS * H];
__device__ __align__(16) float g_tableB[NKEYS * H];
__device__ int g_key[N_NODES];

// ---------------------------------------------------------------------------
// helpers
// ---------------------------------------------------------------------------
__device__ __forceinline__ float silu_acc(float v) {        // accurate (epilogue)
    return __fdividef(v, 1.0f + __expf(-v));
}
__device__ __forceinline__ float silu_tanh(float v) {       // 1 MUFU (GEMM-input path)
    float t;
    asm("tanh.approx.f32 %0, %1;" : "=f"(t) : "f"(0.5f * v));
    return fmaf(0.5f * v, t, 0.5f * v);
}
__device__ __forceinline__ uint32_t pack_h2(float lo, float hi) {
    __half2 h = __floats2half2_rn(lo, hi);
    return *reinterpret_cast<uint32_t*>(&h);
}

// fp16 m16n8k16, f32 accumulate
__device__ __forceinline__ void mma_f16(float (&d)[4],
                                        uint32_t a0, uint32_t a1, uint32_t a2, uint32_t a3,
                                        uint32_t b0, uint32_t b1) {
    asm volatile(
        "mma.sync.aligned.m16n8k16.row.col.f32.f16.f16.f32 "
        "{%0,%1,%2,%3}, {%4,%5,%6,%7}, {%8,%9}, {%0,%1,%2,%3};\n"
        : "+f"(d[0]), "+f"(d[1]), "+f"(d[2]), "+f"(d[3])
        : "r"(a0), "r"(a1), "r"(a2), "r"(a3), "r"(b0), "r"(b1));
}

// ---------------------------------------------------------------------------
// kernel 1: key[n] = x[n]*3 + s[n]
// ---------------------------------------------------------------------------
__global__ void key_kernel(const int* __restrict__ x, const int* __restrict__ s) {
    int n = blockIdx.x * blockDim.x + threadIdx.x;
    if (n < N_NODES) g_key[n] = x[n] * 3 + s[n];
}

// ---------------------------------------------------------------------------
// kernel 2: per-(type,spin) tables (fp32, exact)
// ---------------------------------------------------------------------------
__global__ void table_kernel(const float* __restrict__ emb_w,
                             const float* __restrict__ spin_w,
                             const float* __restrict__ spin_b,
                             const float* __restrict__ lin_w,
                             const float* __restrict__ lin_b) {
    __shared__ float sh[H];
    const int b = blockIdx.x;
    const int t = b / 3, c = b % 3;
    const int tid = threadIdx.x, lane = tid & 31, w = tid >> 5;
    sh[tid] = emb_w[t * H + tid];
    const float sp0 = spin_w[0 * 3 + c] + spin_b[0];
    const float sp1 = spin_w[1 * 3 + c] + spin_b[1];
    const float sp2 = spin_w[2 * 3 + c] + spin_b[2];
    __syncthreads();
    for (int o = w * 32; o < w * 32 + 32; o++) {
        const float* row = lin_w + o * 390;
        float pa = 0.f, pb = 0.f;
#pragma unroll
        for (int u = 0; u < 4; u++) {
            int k = lane * 4 + u;
            pa += row[k] * sh[k];
            pb += row[131 + k] * sh[k];
        }
#pragma unroll
        for (int d = 16; d > 0; d >>= 1) {
            pa += __shfl_xor_sync(0xffffffffu, pa, d);
            pb += __shfl_xor_sync(0xffffffffu, pb, d);
        }
        if (lane == 0) {
            float sa = sp0 * row[128] + sp1 * row[129] + sp2 * row[130];
            float sb = sp0 * row[259] + sp1 * row[260] + sp2 * row[261];
            g_tableA[b * H + o] = pa + sa + lin_b[o];
            g_tableB[b * H + o] = pb + sb;
        }
    }
}

// ---------------------------------------------------------------------------
// kernel 3: persistent edge kernel — fp16 m16n8k16, register epilogue
//
// A fragments (fp16x2 words): block (mt 0..3, kc 0..7) = 132 words (pad 4);
//   word = (mt*8+kc)*132 + lane*4 + reg,  lane = g*4+tg, reg = 2*pb + hi
// W fragments (uint2): [(kc*16+nt)*32 + lane] = {b0,b1}
// Accumulator acc[mi][j][r]: row = wm*32 + mi*16 + g + 8*(r>>1),
//                            col = (wn*8+j)*8 + 2*tg + (r&1)
// ---------------------------------------------------------------------------
struct EdgeSmem {
    uint2    Wf[8 * 16 * 32];        // 32768 B  W fp16 fragments
    uint32_t Af[4 * 8 * 132];        // 16896 B  A fp16 fragments (132-word blocks)
    float    rb[TM * 8];             //  2048 B
    int kA[TM];
    int kB[TM];                      //   512 B
};                                   // 52224 B -> 4 CTAs/SM

__global__ __launch_bounds__(128, 4) void edge_kernel(
    const float* __restrict__ rbf,
    const int* __restrict__ gi,
    const int* __restrict__ gj,
    const float* __restrict__ rbf_w,
    const float* __restrict__ rbf_b,
    const float* __restrict__ lin_w,
    float* __restrict__ out) {
    extern __shared__ __align__(16) char smem_raw[];
    EdgeSmem& S = *reinterpret_cast<EdgeSmem*>(smem_raw);

    const int tid  = threadIdx.x;
    const int lane = tid & 31;
    const int wid  = tid >> 5;
    const int g    = lane >> 2;
    const int tg   = lane & 3;
    const int wm   = wid & 1;   // m-half (32 rows)
    const int wn   = wid >> 1;  // n-half (64 cols)

    // ---- stage W fragments (fp16), pre-permuted into mma B layout ----------
    for (int e = tid; e < 8 * 16 * 32; e += 128) {
        const int ln = e & 31, nt = (e >> 5) & 15, kc = e >> 9;
        const int n  = nt * 8 + (ln >> 2);
        const int k0 = kc * 16 + 2 * (ln & 3);
        const float* p = lin_w + n * 390 + 262 + k0;
        S.Wf[e] = make_uint2(pack_h2(p[0], p[1]), pack_h2(p[8], p[9]));
    }

    // ---- per-thread rbf weights (thread owns cols k0=2c, k0+1; row half hh)
    const int c  = tid & 63;
    const int hh = tid >> 6;
    const int k0 = 2 * c;
    float w0[RDIM], w1[RDIM];
#pragma unroll
    for (int q = 0; q < RDIM; q++) {
        w0[q] = rbf_w[k0 * RDIM + q];
        w1[q] = rbf_w[(k0 + 1) * RDIM + q];
    }
    const float bia0 = rbf_b[k0], bia1 = rbf_b[k0 + 1];
    // phase-2 A-fragment address pieces (fixed per thread)
    const int kc_t = c >> 3;
    const int p_t  = c & 7;
    const int tg_t = p_t & 3;
    const int pb_t = p_t >> 2;
    __syncthreads();

    for (int tile = blockIdx.x; tile < NTILES; tile += gridDim.x) {
        const int e0 = tile * TM;

        // -- phase 1: keys + rbf tile ---------------------------------------
        if (tid < TM) {
            S.kA[tid] = g_key[__ldg(gi + e0 + tid)];
            S.kB[tid] = g_key[__ldg(gj + e0 + tid)];
        }
        for (int idx = tid; idx < TM * RDIM; idx += 128)
            S.rb[(idx / RDIM) * 8 + (idx % RDIM)] = rbf[(size_t)e0 * RDIM + idx];
        __syncthreads();

        // -- phase 2: R = silu(rbf @ rbf_w^T + b), packed fp16x2 fragments --
#pragma unroll 4
        for (int r = 0; r < 32; r++) {
            const int m = hh * 32 + r;
            float z0 = bia0, z1 = bia1;
#pragma unroll
            for (int q = 0; q < RDIM; q++) {
                const float rv = S.rb[m * 8 + q];
                z0 = fmaf(rv, w0[q], z0);
                z1 = fmaf(rv, w1[q], z1);
            }
            const int mt = m >> 4, r16 = m & 15;
            const int hi = r16 >> 3, gg = r16 & 7;
            const int word = (mt * 8 + kc_t) * 132 + (gg * 4 + tg_t) * 4 + 2 * pb_t + hi;
            S.Af[word] = pack_h2(silu_tanh(z0), silu_tanh(z1));
        }
        __syncthreads();

        // -- phase 3: GEMM, warp (wm,wn) does C[wm*32..+32][wn*64..+64] -----
        float acc[2][8][4];
#pragma unroll
        for (int mi = 0; mi < 2; mi++)
#pragma unroll
            for (int j = 0; j < 8; j++) {
                acc[mi][j][0] = 0.f; acc[mi][j][1] = 0.f;
                acc[mi][j][2] = 0.f; acc[mi][j][3] = 0.f;
            }
        const uint4* A4 = reinterpret_cast<const uint4*>(S.Af);
#pragma unroll
        for (int kc = 0; kc < 8; kc++) {
            const uint4 av0 = A4[((wm * 2 + 0) * 8 + kc) * 33 + lane];
            const uint4 av1 = A4[((wm * 2 + 1) * 8 + kc) * 33 + lane];
#pragma unroll
            for (int j = 0; j < 8; j++) {
                const uint2 wv = S.Wf[(kc * 16 + wn * 8 + j) * 32 + lane];
                mma_f16(acc[0][j], av0.x, av0.y, av0.z, av0.w, wv.x, wv.y);
                mma_f16(acc[1][j], av1.x, av1.y, av1.z, av1.w, wv.x, wv.y);
            }
        }

        // -- phase 4: epilogue straight from accumulators -------------------
#pragma unroll
        for (int mi = 0; mi < 2; mi++) {
#pragma unroll
            for (int hi = 0; hi < 2; hi++) {
                const int row = wm * 32 + mi * 16 + hi * 8 + g;
                const float2* pa = reinterpret_cast<const float2*>(g_tableA + S.kA[row] * H) + tg;
                const float2* pb = reinterpret_cast<const float2*>(g_tableB + S.kB[row] * H) + tg;
                float2* po = reinterpret_cast<float2*>(out + (size_t)(e0 + row) * H) + tg;
#pragma unroll
                for (int j = 0; j < 8; j++) {
                    const int ci = (wn * 8 + j) * 4;
                    const float2 a = __ldg(pa + ci);
                    const float2 b = __ldg(pb + ci);
                    float2 o;
                    o.x = silu_acc(a.x + b.x + acc[mi][j][2 * hi + 0]);
                    o.y = silu_acc(a.y + b.y + acc[mi][j][2 * hi + 1]);
                    po[ci] = o;
                }
            }
        }
        __syncthreads();   // protect kA/kB/rb/Af before next tile overwrites
    }
}

// ---------------------------------------------------------------------------
extern "C" void kernel_launch(void* const* d_in, const int* in_sizes, int n_in,
                              void* d_out, int out_size) {
    const int*   x      = (const int*)d_in[0];
    const int*   s      = (const int*)d_in[1];
    const float* rbf    = (const float*)d_in[2];
    const int*   gi     = (const int*)d_in[3];
    const int*   gj     = (const int*)d_in[4];
    const float* emb_w  = (const float*)d_in[5];
    const float* spin_w = (const float*)d_in[6];
    const float* spin_b = (const float*)d_in[7];
    const float* rbf_w  = (const float*)d_in[8];
    const float* rbf_b  = (const float*)d_in[9];
    const float* lin_w  = (const float*)d_in[10];
    const float* lin_b  = (const float*)d_in[11];
    float* out = (float*)d_out;

    key_kernel<<<(N_NODES + 255) / 256, 256>>>(x, s);
    table_kernel<<<NKEYS, 128>>>(emb_w, spin_w, spin_b, lin_w, lin_b);

    const int smem = (int)sizeof(EdgeSmem);
    cudaFuncSetAttribute(edge_kernel, cudaFuncAttributeMaxDynamicSharedMemorySize, smem);
    edge_kernel<<<GRID, 128, smem>>>(rbf, gi, gj, rbf_w, rbf_b, lin_w, out);
}